// round 5
// baseline (speedup 1.0000x reference)
#include <cuda_runtime.h>

#define N     8192
#define D     256
#define D4    64            // D/4
#define NCLS  10
#define NB    512           // accumulate blocks
#define RPB   16            // rows per block
#define SG    4             // subgroups (64 threads each)
#define RPSG  4             // rows per subgroup
#define NSEG  16            // reduce segments
#define BPSEG (NB / NSEG)   // 32 partials per segment
#define SDIM  (NCLS * D)    // 2560
#define K2_BLOCKS (11 * NSEG)

// Scratch (fully overwritten every launch -> graph-replay safe).
__device__ float g_partS[NB][SDIM];
__device__ float g_partQ[NB][NCLS];
__device__ int   g_partC[NB][NCLS];
__device__ float g_redS[NSEG][SDIM];
__device__ float g_redQ[NSEG][NCLS];
__device__ int   g_redC[NSEG][NCLS];
__device__ int   g_ctr;                 // 0 at load; last block resets to 0

// ---------------------------------------------------------------------------
// Kernel 1: stream the 8 MB input once. Labels are UNIFORM across each
// 64-thread subgroup per row, so a warp-uniform branch tree touches exactly
// one class accumulator per row (no 10-way predicated masking).
// ---------------------------------------------------------------------------
__global__ void __launch_bounds__(256) k_accum(const float* __restrict__ x,
                                               const int* __restrict__ lab) {
    __shared__ float4 Ssh[SG][NCLS * D4];   // 40 KB: one buffer per subgroup
    __shared__ float  qred[8][NCLS];
    __shared__ int    labs[RPB];

    const int tid = threadIdx.x;
    const int g   = tid >> 6;               // subgroup 0..3
    const int t   = tid & 63;               // dim-group 0..63
    const int b   = blockIdx.x;

    if (tid < RPB) labs[tid] = lab[b * RPB + tid];
    __syncthreads();

    float4 S[NCLS];
    float  Q[NCLS];
    #pragma unroll
    for (int k = 0; k < NCLS; k++) {
        S[k] = make_float4(0.f, 0.f, 0.f, 0.f);
        Q[k] = 0.f;
    }

    const float4* __restrict__ p =
        reinterpret_cast<const float4*>(x) + (size_t)(b * RPB + g * RPSG) * D4 + t;

    // Front-batch the loads, then branch per row on the uniform label.
    float4 v[RPSG];
    #pragma unroll
    for (int r = 0; r < RPSG; r++) v[r] = p[r * D4];

#define BODY(k) { S[k].x += v[r].x; S[k].y += v[r].y;                          \
                  S[k].z += v[r].z; S[k].w += v[r].w; Q[k] += q; }
    #pragma unroll
    for (int r = 0; r < RPSG; r++) {
        const int l = labs[g * RPSG + r];
        float q = v[r].x * v[r].x;
        q = fmaf(v[r].y, v[r].y, q);
        q = fmaf(v[r].z, v[r].z, q);
        q = fmaf(v[r].w, v[r].w, q);
        if      (l == 0) BODY(0)
        else if (l == 1) BODY(1)
        else if (l == 2) BODY(2)
        else if (l == 3) BODY(3)
        else if (l == 4) BODY(4)
        else if (l == 5) BODY(5)
        else if (l == 6) BODY(6)
        else if (l == 7) BODY(7)
        else if (l == 8) BODY(8)
        else             BODY(9)
    }
#undef BODY

    // Each subgroup writes its private buffer (no serialization).
    #pragma unroll
    for (int k = 0; k < NCLS; k++) Ssh[g][k * D4 + t] = S[k];
    __syncthreads();

    // Cooperative merge of 4 buffers + dump (10 KB/block, no atomics).
    float4* dst = reinterpret_cast<float4*>(g_partS[b]);
    #pragma unroll
    for (int i = tid; i < NCLS * D4; i += 256) {
        float4 a = Ssh[0][i], b1 = Ssh[1][i], c = Ssh[2][i], d = Ssh[3][i];
        a.x += b1.x; a.y += b1.y; a.z += b1.z; a.w += b1.w;
        c.x += d.x;  c.y += d.y;  c.z += d.z;  c.w += d.w;
        a.x += c.x;  a.y += c.y;  a.z += c.z;  a.w += c.w;
        dst[i] = a;
    }

    // Q reduce: shfl within each warp, then threads 0..9 sum the 8 warps.
    const int lane = tid & 31, w = tid >> 5;
    #pragma unroll
    for (int k = 0; k < NCLS; k++) {
        float vq = Q[k];
        #pragma unroll
        for (int off = 16; off; off >>= 1)
            vq += __shfl_down_sync(0xffffffffu, vq, off);
        if (lane == 0) qred[w][k] = vq;
    }
    __syncthreads();
    if (tid < NCLS) {
        float s = 0.f;
        #pragma unroll
        for (int w2 = 0; w2 < 8; w2++) s += qred[w2][tid];
        g_partQ[b][tid] = s;
    }

    // Per-block class counts via ballot over the 16 cached labels.
    if (tid < 32) {
        int l = (tid < RPB) ? labs[tid] : -1;
        #pragma unroll
        for (int k = 0; k < NCLS; k++) {
            unsigned m = __ballot_sync(0xffffffffu, l == k);
            if (tid == 0) g_partC[b][k] = __popc(m);
        }
    }
}

// ---------------------------------------------------------------------------
// Kernel 2: segment-reduce the 512 partials, then the LAST block (atomic
// counter) runs the epilogue. One launch instead of two.
// ---------------------------------------------------------------------------
__device__ __forceinline__ double block_reduce(double v, double* red, int t) {
    __syncthreads();
    red[t] = v;
    __syncthreads();
    #pragma unroll
    for (int s2 = 128; s2; s2 >>= 1) {
        if (t < s2) red[t] += red[t + s2];
        __syncthreads();
    }
    return red[0];
}

__global__ void __launch_bounds__(256) k_reduce_final(const float* __restrict__ x,
                                                      const int* __restrict__ lab,
                                                      float* __restrict__ res) {
    const int bx  = blockIdx.x;   // 0..10
    const int s   = blockIdx.y;   // segment 0..15
    const int tid = threadIdx.x;
    const int b0  = s * BPSEG;

    if (bx < 10) {
        const int gid = bx * 256 + tid;      // 0..2559
        float acc = 0.f;
        #pragma unroll
        for (int i = 0; i < BPSEG; i++) acc += g_partS[b0 + i][gid];
        g_redS[s][gid] = acc;
    } else {
        if (tid < NCLS) {
            float acc = 0.f;
            #pragma unroll
            for (int i = 0; i < BPSEG; i++) acc += g_partQ[b0 + i][tid];
            g_redQ[s][tid] = acc;
        } else if (tid < 2 * NCLS) {
            const int l = tid - NCLS;
            int acc = 0;
            #pragma unroll
            for (int i = 0; i < BPSEG; i++) acc += g_partC[b0 + i][l];
            g_redC[s][l] = acc;
        }
    }

    // Last-block election.
    __shared__ int isLast;
    __threadfence();
    __syncthreads();
    if (tid == 0) {
        int prev = atomicAdd(&g_ctr, 1);
        isLast = (prev == K2_BLOCKS - 1) ? 1 : 0;
    }
    __syncthreads();
    if (!isLast) return;

    // ---------------- Epilogue (single block, thread t = dim t) ------------
    __shared__ double red[256];
    __shared__ float  Qs[NCLS];
    __shared__ int    Cs[NCLS];

    const int t = tid;
    if (t < NCLS) {
        float q = 0.f; int c = 0;
        #pragma unroll
        for (int sg = 0; sg < NSEG; sg++) { q += g_redQ[sg][t]; c += g_redC[sg][t]; }
        Qs[t] = q; Cs[t] = c;
    }
    const int firstL = lab[0];
    const int lastL  = lab[N - 1];
    const float v0 = x[t];
    const float vN = x[(size_t)(N - 1) * D + t];
    __syncthreads();

    double dsame = 0.0;
    float satot = 0.f, sbtot = 0.f;
    #pragma unroll
    for (int l = 0; l < NCLS; l++) {
        float sv = 0.f;
        #pragma unroll
        for (int sg = 0; sg < NSEG; sg++) sv += g_redS[sg][l * D + t];
        float sa = sv - ((l == lastL)  ? vN : 0.f);   // rows i in [0, N-1)
        float sb = sv - ((l == firstL) ? v0 : 0.f);   // cols j in [1, N)
        dsame += (double)sa * (double)sb;
        satot += sa; sbtot += sb;
    }
    const double dall = (double)satot * (double)sbtot;

    const double dsame_t = block_reduce(dsame, red, t);
    const double dall_t  = block_reduce(dall,  red, t);
    const double sq0_t   = block_reduce((double)v0 * v0, red, t);
    const double sqN_t   = block_reduce((double)vN * vN, red, t);

    if (t == 0) {
        double term12 = 0.0;
        #pragma unroll
        for (int l = 0; l < NCLS; l++) {
            double sqA = (double)Qs[l] - ((l == lastL)  ? sqN_t : 0.0);
            double sqB = (double)Qs[l] - ((l == firstL) ? sq0_t : 0.0);
            double cA  = (double)(Cs[l] - ((l == lastL)  ? 1 : 0));
            double cB  = (double)(Cs[l] - ((l == firstL) ? 1 : 0));
            term12 += sqA * (2.0 * cB - (double)(N - 1))
                    + sqB * (2.0 * cA - (double)(N - 1));
        }
        double result = term12 - 2.0 * (2.0 * dsame_t - dall_t);
        const double PAR = 0.5 / (double)N;   // COV * 0.5 / BATCH_SIZE
        res[0] = (float)(PAR * result);
        g_ctr = 0;                            // reset for next graph replay
    }
}

extern "C" void kernel_launch(void* const* d_in, const int* in_sizes, int n_in,
                              void* d_out, int out_size) {
    const float* x   = (const float*)d_in[0];
    const int*   lab = (const int*)d_in[1];
    float*       res = (float*)d_out;
    (void)in_sizes; (void)n_in; (void)out_size;

    k_accum<<<NB, 256>>>(x, lab);
    dim3 rg(11, NSEG);
    k_reduce_final<<<rg, 256>>>(x, lab, res);
}